// round 6
// baseline (speedup 1.0000x reference)
#include <cuda_runtime.h>
#include <cuda_bf16.h>
#include <cstdint>

typedef unsigned long long ull;

// ---------------- problem constants ----------------
#define BSZ 2
#define SEQ 2048
#define HID 2048
#define HD  256
#define NH  8
#define SCALING 0.0625f

// ---------------- scratch (device globals) ----------------
__device__ float g_Qp [(long)BSZ*SEQ*NH*HD];   // pre-RoPE Q (b,s,h,d)
__device__ float g_Q  [(long)BSZ*NH*SEQ*HD];   // RoPE'd, scaled Q (b,h,s,d)
__device__ float g_KV [(long)BSZ*SEQ*512];     // [token][0:256]=K, [256:512]=V
__device__ float g_Kt [(long)BSZ*HD*SEQ];      // K^T per batch (d, s2)
__device__ float g_AO [(long)BSZ*SEQ*NH*HD];   // attn out (b,s,h*d)
__device__ float g_Wkv[(long)HID*512];         // [Wk | Wv]

// ---------------- helpers ----------------
__device__ __forceinline__ uint32_t smem_u32(const void* p) {
    uint32_t a;
    asm("{ .reg .u64 t; cvta.to.shared.u64 t, %1; cvt.u32.u64 %0, t; }" : "=r"(a) : "l"(p));
    return a;
}
__device__ __forceinline__ void cp_async16(uint32_t dst, const void* src) {
    asm volatile("cp.async.cg.shared.global [%0], [%1], 16;" :: "r"(dst), "l"(src));
}
__device__ __forceinline__ void cp_commit() { asm volatile("cp.async.commit_group;"); }
template<int N> __device__ __forceinline__ void cp_wait() {
    asm volatile("cp.async.wait_group %0;" :: "n"(N));
}
__device__ __forceinline__ ull pk2(float x) {
    ull r; unsigned u = __float_as_uint(x);
    asm("mov.b64 %0, {%1, %1};" : "=l"(r) : "r"(u));
    return r;
}
__device__ __forceinline__ ull fma2(ull a, ull b, ull c) {
    ull d;
    asm("fma.rn.f32x2 %0, %1, %2, %3;" : "=l"(d) : "l"(a), "l"(b), "l"(c));
    return d;
}
__device__ __forceinline__ float2 unpk2(ull v) {
    unsigned lo, hi;
    asm("mov.b64 {%0, %1}, %2;" : "=r"(lo), "=r"(hi) : "l"(v));
    return make_float2(__uint_as_float(lo), __uint_as_float(hi));
}

// ---------------- fp32 GEMM: 128x128 tile, BK=16, 4-stage cp.async ----------
// C = A(M x K) * B(K x N); A row-major(lda), B row-major(ldb), C row-major(ldc)
// batched: A += z*sAz ; B += b*sBb ; C += b*sCb + h*sCh, b=z/nh, h=z%nh
// causalQK: skip tiles colT > rowT ; causalPV: truncate K at (rowT+1)*128
#define NSTG 4
// per stage: A 128x16 floats (8KB) + B 16x128 floats (8KB)
#define STG_FLOATS 4096
#define SMEM_DYN (NSTG * STG_FLOATS * 4)

__global__ __launch_bounds__(256, 2)
void sgemm2(const float* __restrict__ A, const float* __restrict__ B,
            float* __restrict__ C,
            int K, int lda, int ldb, int ldc,
            long sAz, long sBb, long sCb, long sCh, int nh,
            int causalQK, int causalPV)
{
    extern __shared__ float sm[];
    const int tid = threadIdx.x;
    const int z = blockIdx.z, b = z / nh, h = z - b * nh;
    const int rowT = blockIdx.y, colT = blockIdx.x;
    if (causalQK && colT > rowT) return;

    A += (long)z * sAz + (long)(rowT * 128) * lda;
    B += (long)b * sBb + colT * 128;
    C += (long)b * sCb + (long)h * sCh;

    const int Keff = causalPV ? min(K, (rowT + 1) * 128) : K;
    const int nk = Keff >> 4;

    const uint32_t smb = smem_u32(sm);
    const int tr = tid >> 4;       // 0..15
    const int tc = tid & 15;       // 0..15

    // cp.async segment ids
    const int am0 = tid >> 2,       ak0 = (tid & 3) << 2;       // A seg tid
    const int am1 = am0 + 64;                                    // A seg tid+256
    const int bk0 = tid >> 5,       bn0 = (tid & 31) << 2;      // B seg tid
    const int bk1 = bk0 + 8;                                     // B seg tid+256

    ull acc[8][4];
    #pragma unroll
    for (int m = 0; m < 8; m++)
        #pragma unroll
        for (int n = 0; n < 4; n++) acc[m][n] = 0ull;

    // issue stage loads for chunk c into stage slot st
    #define ISSUE(st, c) do {                                                   \
        uint32_t sa_ = smb + (st) * (STG_FLOATS * 4);                            \
        uint32_t sb_ = sa_ + 8192;                                               \
        const float* Ag = A + (c) * 16;                                          \
        const float* Bg = B + (long)((c) * 16) * ldb;                            \
        cp_async16(sa_ + (am0 * 16 + ak0) * 4, Ag + (long)am0 * lda + ak0);      \
        cp_async16(sa_ + (am1 * 16 + ak0) * 4, Ag + (long)am1 * lda + ak0);      \
        cp_async16(sb_ + (bk0 * 128 + bn0) * 4, Bg + (long)bk0 * ldb + bn0);     \
        cp_async16(sb_ + (bk1 * 128 + bn0) * 4, Bg + (long)bk1 * ldb + bn0);     \
    } while (0)

    // prologue: stages 0..NSTG-2
    #pragma unroll
    for (int s = 0; s < NSTG - 1; s++) {
        if (s < nk) ISSUE(s, s);
        cp_commit();
    }

    for (int i = 0; i < nk; i++) {
        cp_wait<NSTG - 2>();
        __syncthreads();

        const int stg = i & (NSTG - 1);
        const float* sa = sm + stg * STG_FLOATS;
        const float* sbp = sa + 2048;

        #pragma unroll
        for (int k2 = 0; k2 < 8; k2++) {          // pairs of k
            float2 a2[8];
            #pragma unroll
            for (int hf = 0; hf < 2; hf++)
                #pragma unroll
                for (int j = 0; j < 4; j++) {
                    const int m = hf * 64 + tr * 4 + j;
                    a2[hf * 4 + j] = *(const float2*)(sa + m * 16 + k2 * 2);
                }
            #pragma unroll
            for (int kk = 0; kk < 2; kk++) {
                const int k = k2 * 2 + kk;
                ulonglong2 bv0 = *(const ulonglong2*)(sbp + k * 128 + tc * 4);
                ulonglong2 bv1 = *(const ulonglong2*)(sbp + k * 128 + 64 + tc * 4);
                ull bn_[4] = { bv0.x, bv0.y, bv1.x, bv1.y };
                ull am_[8];
                #pragma unroll
                for (int m = 0; m < 8; m++)
                    am_[m] = pk2(kk ? a2[m].y : a2[m].x);
                #pragma unroll
                for (int m = 0; m < 8; m++)
                    #pragma unroll
                    for (int n = 0; n < 4; n++)
                        acc[m][n] = fma2(am_[m], bn_[n], acc[m][n]);
            }
        }

        const int nc = i + NSTG - 1;
        if (nc < nk) ISSUE((i + NSTG - 1) & (NSTG - 1), nc);
        cp_commit();
    }
    #undef ISSUE

    // epilogue
    #pragma unroll
    for (int m = 0; m < 8; m++) {
        const int r = rowT * 128 + ((m < 4) ? (tr * 4 + m) : (64 + tr * 4 + m - 4));
        float* cp = C + (long)r * ldc + colT * 128;
        #pragma unroll
        for (int n = 0; n < 4; n++) {
            const int c = (n < 2) ? (tc * 4 + 2 * n) : (64 + tc * 4 + 2 * (n - 2));
            float2 v = unpk2(acc[m][n]);
            *(float2*)(cp + c) = v;
        }
    }
}

// ---------------- weight concat [Wk | Wv] ----------------
__global__ void concat_wkv(const float* __restrict__ Wk, const float* __restrict__ Wv,
                           float* __restrict__ Wkv) {
    int idx = blockIdx.x * 256 + threadIdx.x;      // HID*512
    int k = idx >> 9, n = idx & 511;
    Wkv[idx] = (n < 256) ? Wk[k * 256 + n] : Wv[k * 256 + (n - 256)];
}

// ---------------- RoPE Q: one block per (b,s) token; coalesced ----------------
__global__ __launch_bounds__(256)
void rope_q(const float* __restrict__ Qp, const float* __restrict__ cosb,
            const float* __restrict__ sinb, float* __restrict__ Qt) {
    const int bs = blockIdx.x;            // 0..4095
    const int b = bs >> 11, s = bs & 2047;
    const int tid = threadIdx.x;          // = d, 0..255
    __shared__ float cs_[256], sn_[256];
    cs_[tid] = cosb[(long)bs * 256 + tid];
    sn_[tid] = sinb[(long)bs * 256 + tid];
    __syncthreads();

    const float* src = Qp + (long)bs * 2048;
    const int d = tid;
    const int dp = (d < 128) ? d + 128 : d - 128;
    const float cd = cs_[d], sd = sn_[d];
    #pragma unroll
    for (int h = 0; h < 8; h++) {
        const float x  = src[h * 256 + d];
        const float xp = src[h * 256 + dp];
        const float rot = (d < 128) ? -xp : xp;
        Qt[(((long)(b * 8 + h) * 2048 + s) << 8) + d] = (x * cd + rot * sd) * SCALING;
    }
}

// ---------------- RoPE K + transpose -> Kt (b, d, s2), smem 32x32 -----------
__global__ void rope_kT(const float* __restrict__ KV, const float* __restrict__ cosb,
                        const float* __restrict__ sinb, float* __restrict__ Kt) {
    __shared__ float t[32][33];
    const int b = blockIdx.z;
    const int d0 = blockIdx.y * 32;
    const int s0 = blockIdx.x * 32;
    const int tx = threadIdx.x, ty = threadIdx.y;

    const int d = d0 + tx;
    const int s2 = s0 + ty;
    const int dp = (d < 128) ? d + 128 : d - 128;
    const long tok = (long)(b * SEQ + s2);
    const float x  = KV[tok * 512 + d];
    const float xp = KV[tok * 512 + dp];
    const float rot = (d < 128) ? -xp : xp;
    const float c = cosb[tok * 256 + d];
    const float sv = sinb[tok * 256 + d];
    t[ty][tx] = x * c + rot * sv;
    __syncthreads();

    Kt[((long)(b * HD + d0 + ty)) * SEQ + s0 + tx] = t[tx][ty];
}

// ---------------- causal softmax: row r uses first r+1 logits ----------------
__global__ __launch_bounds__(256)
void softmax_causal(float* __restrict__ W) {
    const long row = blockIdx.x;                 // (b,h,s1) flat
    const int r = (int)(row & 2047);
    const int len = r + 1;
    float* p = W + row * (long)SEQ;
    const int tid = threadIdx.x;
    __shared__ float red[256];

    float v[8];
    float m = -3.0e38f;
    #pragma unroll
    for (int j = 0; j < 8; j++) {
        const int c = tid + j * 256;
        v[j] = (c < len) ? p[c] : -3.0e38f;
        m = fmaxf(m, v[j]);
    }
    red[tid] = m; __syncthreads();
    for (int s = 128; s > 0; s >>= 1) {
        if (tid < s) red[tid] = fmaxf(red[tid], red[tid + s]);
        __syncthreads();
    }
    m = red[0]; __syncthreads();

    float sum = 0.0f;
    #pragma unroll
    for (int j = 0; j < 8; j++) {
        const int c = tid + j * 256;
        v[j] = (c < len) ? __expf(v[j] - m) : 0.0f;
        sum += v[j];
    }
    red[tid] = sum; __syncthreads();
    for (int s = 128; s > 0; s >>= 1) {
        if (tid < s) red[tid] += red[tid + s];
        __syncthreads();
    }
    const float inv = 1.0f / red[0]; __syncthreads();

    #pragma unroll
    for (int j = 0; j < 8; j++) {
        const int c = tid + j * 256;
        p[c] = v[j] * inv;          // exact 0 above diagonal
    }
}

// ---------------- launch ----------------
extern "C" void kernel_launch(void* const* d_in, const int* in_sizes, int n_in,
                              void* d_out, int out_size)
{
    const float* hs   = (const float*)d_in[0];
    const float* cosb = (const float*)d_in[1];
    const float* sinb = (const float*)d_in[2];
    const float* Wq   = (const float*)d_in[4];
    const float* Wk   = (const float*)d_in[5];
    const float* Wv   = (const float*)d_in[6];
    const float* Wo   = (const float*)d_in[7];

    float* out_attn = (float*)d_out;                          // (B,S,H)
    float* out_w    = (float*)d_out + (long)BSZ * SEQ * HID;  // (B,NH,S,S)

    const long SS = (long)SEQ * SEQ;

    cudaFuncSetAttribute(sgemm2, cudaFuncAttributeMaxDynamicSharedMemorySize, SMEM_DYN);

    // 0) concat K/V weights
    concat_wkv<<<(HID * 512) / 256, 256>>>(Wk, Wv, g_Wkv);

    // 1) Q projection: (4096 x 2048) @ (2048 x 2048)
    sgemm2<<<dim3(16, 32, 1), 256, SMEM_DYN>>>(hs, Wq, g_Qp,
        HID, HID, HID, HID, 0, 0, 0, 0, 1, 0, 0);

    // 2) KV projection: (4096 x 2048) @ (2048 x 512)
    sgemm2<<<dim3(4, 32, 1), 256, SMEM_DYN>>>(hs, g_Wkv, g_KV,
        HID, HID, 512, 512, 0, 0, 0, 0, 1, 0, 0);

    // 3) RoPE Q (+transpose+scale), RoPE K (+transpose)
    rope_q <<<4096, 256>>>(g_Qp, cosb, sinb, g_Q);
    rope_kT<<<dim3(64, 8, 2), dim3(32, 32)>>>(g_KV, cosb, sinb, g_Kt);

    // 4) logits = Q K^T (scaled via Q), causal tile skip
    sgemm2<<<dim3(16, 16, 16), 256, SMEM_DYN>>>(g_Q, g_Kt, out_w,
        HD, HD, SEQ, SEQ,
        (long)SEQ * HD, (long)HD * SEQ, (long)NH * SS, SS, NH, 1, 0);

    // 5) causal softmax (exact zeros above diagonal)
    softmax_causal<<<32768, 256>>>(out_w);

    // 6) attn = P @ V, K-loop truncated by causality
    sgemm2<<<dim3(2, 16, 16), 256, SMEM_DYN>>>(out_w, g_KV + 256, g_AO,
        SEQ, SEQ, 512, HID,
        SS, (long)SEQ * 512, (long)SEQ * HID, (long)HD, NH, 0, 1);

    // 7) output projection: (4096 x 2048) @ (2048 x 2048)
    sgemm2<<<dim3(16, 32, 1), 256, SMEM_DYN>>>(g_AO, Wo, out_attn,
        HID, HID, HID, HID, 0, 0, 0, 0, 1, 0, 0);
}

// round 7
// speedup vs baseline: 2.0310x; 2.0310x over previous
#include <cuda_runtime.h>
#include <cuda_bf16.h>
#include <cstdint>

typedef unsigned long long ull;

// ---------------- problem constants ----------------
#define BSZ 2
#define SEQ 2048
#define HID 2048
#define HD  256
#define NH  8
#define SCALING 0.0625f

// ---------------- scratch (device globals) ----------------
__device__ float g_Qp [(long)BSZ*SEQ*NH*HD];   // pre-RoPE Q (b,s,h,d)
__device__ float g_Q  [(long)BSZ*NH*SEQ*HD];   // RoPE'd, scaled Q (b,h,s,d)
__device__ float g_KV [(long)BSZ*SEQ*512];     // [token][0:256]=K, [256:512]=V
__device__ float g_Kt [(long)BSZ*HD*SEQ];      // K^T per batch (d, s2)
__device__ float g_AO [(long)BSZ*SEQ*NH*HD];   // attn out (b,s,h*d)
__device__ float g_Wkv[(long)HID*512];         // [Wk | Wv]

// ---------------- f32x2 helpers ----------------
__device__ __forceinline__ ull pk2(float x) {
    ull r; unsigned u = __float_as_uint(x);
    asm("mov.b64 %0, {%1, %1};" : "=l"(r) : "r"(u));
    return r;
}
__device__ __forceinline__ ull fma2(ull a, ull b, ull c) {
    ull d;
    asm("fma.rn.f32x2 %0, %1, %2, %3;" : "=l"(d) : "l"(a), "l"(b), "l"(c));
    return d;
}
__device__ __forceinline__ float2 unpk2(ull v) {
    unsigned lo, hi;
    asm("mov.b64 {%0, %1}, %2;" : "=r"(lo), "=r"(hi) : "l"(v));
    return make_float2(__uint_as_float(lo), __uint_as_float(hi));
}

// ---------------- fp32 GEMM, 128x128 tile, BK=16, f32x2, frag-pipelined -----
// C = A(M x K) * B(K x N); all row-major. batched via gridDim.z.
// causalQK: skip tiles colT > rowT ; causalPV: truncate K at (rowT+1)*128
#define BK 16

__global__ __launch_bounds__(256)
void sgemm2(const float* __restrict__ A, const float* __restrict__ B,
            float* __restrict__ C,
            int K, int lda, int ldb, int ldc,
            long sAz, long sBb, long sCb, long sCh, int nh,
            int causalQK, int causalPV)
{
    __shared__ float As[2][BK][128];
    __shared__ float Bs[2][BK][128];

    const int tid = threadIdx.x;
    const int z = blockIdx.z, b = z / nh, h = z - b * nh;
    const int rowT = blockIdx.y, colT = blockIdx.x;
    if (causalQK && colT > rowT) return;

    A += (long)z * sAz + (long)(rowT * 128) * lda;
    B += (long)b * sBb + colT * 128;
    C += (long)b * sCb + (long)h * sCh;

    const int Keff = causalPV ? min(K, (rowT + 1) * 128) : K;
    const int nk = Keff >> 4;

    const int tr = tid >> 4;       // 0..15
    const int tc = tid & 15;       // 0..15

    // global prefetch indexing
    const int af0 = tid, af1 = tid + 256;
    const int am0 = af0 >> 2, ak0 = (af0 & 3) << 2;
    const int am1 = af1 >> 2, ak1 = (af1 & 3) << 2;
    const int bk0 = af0 >> 5, bn0 = (af0 & 31) << 2;
    const int bk1 = af1 >> 5, bn1 = (af1 & 31) << 2;

    float4 pa0, pa1, pb0, pb1;
    // stage 0
    pa0 = *(const float4*)(A + (long)am0 * lda + ak0);
    pa1 = *(const float4*)(A + (long)am1 * lda + ak1);
    pb0 = *(const float4*)(B + (long)bk0 * ldb + bn0);
    pb1 = *(const float4*)(B + (long)bk1 * ldb + bn1);
    As[0][ak0 + 0][am0] = pa0.x; As[0][ak0 + 1][am0] = pa0.y;
    As[0][ak0 + 2][am0] = pa0.z; As[0][ak0 + 3][am0] = pa0.w;
    As[0][ak1 + 0][am1] = pa1.x; As[0][ak1 + 1][am1] = pa1.y;
    As[0][ak1 + 2][am1] = pa1.z; As[0][ak1 + 3][am1] = pa1.w;
    *(float4*)&Bs[0][bk0][bn0] = pb0;
    *(float4*)&Bs[0][bk1][bn1] = pb1;
    __syncthreads();

    ull acc[8][4];
    #pragma unroll
    for (int m = 0; m < 8; m++)
        #pragma unroll
        for (int n = 0; n < 4; n++) acc[m][n] = 0ull;

    // fragment registers (current + next) — raw, pk2 at use
    float4 ca0, ca1, na0, na1;
    ulonglong2 cb0, cb1, nb0, nb1;

    // load frag k=0, buf 0
    ca0 = *(const float4*)&As[0][0][tr * 4];
    ca1 = *(const float4*)&As[0][0][64 + tr * 4];
    cb0 = *(const ulonglong2*)&Bs[0][0][tc * 4];
    cb1 = *(const ulonglong2*)&Bs[0][0][64 + tc * 4];

    for (int s = 0; s < nk; s++) {
        const int buf = s & 1;
        if (s + 1 < nk) {
            const float* A1 = A + (s + 1) * BK;
            const float* B1 = B + (long)(s + 1) * BK * ldb;
            pa0 = *(const float4*)(A1 + (long)am0 * lda + ak0);
            pa1 = *(const float4*)(A1 + (long)am1 * lda + ak1);
            pb0 = *(const float4*)(B1 + (long)bk0 * ldb + bn0);
            pb1 = *(const float4*)(B1 + (long)bk1 * ldb + bn1);
        }
        #pragma unroll
        for (int k = 0; k < BK; k++) {
            if (k + 1 < BK) {   // prefetch next frag from same buffer
                na0 = *(const float4*)&As[buf][k + 1][tr * 4];
                na1 = *(const float4*)&As[buf][k + 1][64 + tr * 4];
                nb0 = *(const ulonglong2*)&Bs[buf][k + 1][tc * 4];
                nb1 = *(const ulonglong2*)&Bs[buf][k + 1][64 + tc * 4];
            }
            {
                ull bn_[4] = { cb0.x, cb0.y, cb1.x, cb1.y };
                ull am_[8] = { pk2(ca0.x), pk2(ca0.y), pk2(ca0.z), pk2(ca0.w),
                               pk2(ca1.x), pk2(ca1.y), pk2(ca1.z), pk2(ca1.w) };
                #pragma unroll
                for (int m = 0; m < 8; m++)
                    #pragma unroll
                    for (int n = 0; n < 4; n++)
                        acc[m][n] = fma2(am_[m], bn_[n], acc[m][n]);
            }
            if (k + 1 < BK) { ca0 = na0; ca1 = na1; cb0 = nb0; cb1 = nb1; }
        }
        if (s + 1 < nk) {
            __syncthreads();
            const int nb = buf ^ 1;
            As[nb][ak0 + 0][am0] = pa0.x; As[nb][ak0 + 1][am0] = pa0.y;
            As[nb][ak0 + 2][am0] = pa0.z; As[nb][ak0 + 3][am0] = pa0.w;
            As[nb][ak1 + 0][am1] = pa1.x; As[nb][ak1 + 1][am1] = pa1.y;
            As[nb][ak1 + 2][am1] = pa1.z; As[nb][ak1 + 3][am1] = pa1.w;
            *(float4*)&Bs[nb][bk0][bn0] = pb0;
            *(float4*)&Bs[nb][bk1][bn1] = pb1;
            __syncthreads();
            // load frag k=0 of next buffer
            ca0 = *(const float4*)&As[nb][0][tr * 4];
            ca1 = *(const float4*)&As[nb][0][64 + tr * 4];
            cb0 = *(const ulonglong2*)&Bs[nb][0][tc * 4];
            cb1 = *(const ulonglong2*)&Bs[nb][0][64 + tc * 4];
        }
    }

    // epilogue
    #pragma unroll
    for (int m = 0; m < 8; m++) {
        const int r = rowT * 128 + ((m < 4) ? (tr * 4 + m) : (64 + tr * 4 + m - 4));
        float* cp = C + (long)r * ldc + colT * 128;
        #pragma unroll
        for (int n = 0; n < 4; n++) {
            const int c = (n < 2) ? (tc * 4 + 2 * n) : (64 + tc * 4 + 2 * (n - 2));
            float2 v = unpk2(acc[m][n]);
            *(float2*)(cp + c) = v;
        }
    }
}

// ---------------- weight concat [Wk | Wv] ----------------
__global__ void concat_wkv(const float* __restrict__ Wk, const float* __restrict__ Wv,
                           float* __restrict__ Wkv) {
    int idx = blockIdx.x * 256 + threadIdx.x;      // HID*512
    int k = idx >> 9, n = idx & 511;
    Wkv[idx] = (n < 256) ? Wk[k * 256 + n] : Wv[k * 256 + (n - 256)];
}

// ---------------- RoPE Q: block per token, loads hoisted ----------------
__global__ __launch_bounds__(256)
void rope_q(const float* __restrict__ Qp, const float* __restrict__ cosb,
            const float* __restrict__ sinb, float* __restrict__ Qt) {
    const int bs = blockIdx.x;            // 0..4095
    const int b = bs >> 11, s = bs & 2047;
    const int d = threadIdx.x;            // 0..255
    const int dp = (d < 128) ? d + 128 : d - 128;
    const float cd = cosb[(long)bs * 256 + d];
    const float sd = sinb[(long)bs * 256 + d];
    const float sgn = (d < 128) ? -1.0f : 1.0f;

    const float* src = Qp + (long)bs * 2048;
    float x[8], xp[8];
    #pragma unroll
    for (int h = 0; h < 8; h++) x[h]  = src[h * 256 + d];
    #pragma unroll
    for (int h = 0; h < 8; h++) xp[h] = src[h * 256 + dp];
    #pragma unroll
    for (int h = 0; h < 8; h++) {
        Qt[(((long)(b * 8 + h) * 2048 + s) << 8) + d] =
            (x[h] * cd + sgn * xp[h] * sd) * SCALING;
    }
}

// ---------------- RoPE K + transpose -> Kt (b, d, s2), smem 32x32 -----------
__global__ void rope_kT(const float* __restrict__ KV, const float* __restrict__ cosb,
                        const float* __restrict__ sinb, float* __restrict__ Kt) {
    __shared__ float t[32][33];
    const int b = blockIdx.z;
    const int d0 = blockIdx.y * 32;
    const int s0 = blockIdx.x * 32;
    const int tx = threadIdx.x, ty = threadIdx.y;

    const int d = d0 + tx;
    const int s2 = s0 + ty;
    const int dp = (d < 128) ? d + 128 : d - 128;
    const long tok = (long)(b * SEQ + s2);
    const float x  = KV[tok * 512 + d];
    const float xp = KV[tok * 512 + dp];
    const float rot = (d < 128) ? -xp : xp;
    const float c = cosb[tok * 256 + d];
    const float sv = sinb[tok * 256 + d];
    t[ty][tx] = x * c + rot * sv;
    __syncthreads();

    Kt[((long)(b * HD + d0 + ty)) * SEQ + s0 + tx] = t[tx][ty];
}

// ---------------- causal softmax: row r uses first r+1 logits ----------------
__global__ __launch_bounds__(256)
void softmax_causal(float* __restrict__ W) {
    const long row = blockIdx.x;                 // (b,h,s1) flat
    const int r = (int)(row & 2047);
    const int len = r + 1;
    float* p = W + row * (long)SEQ;
    const int tid = threadIdx.x;
    __shared__ float red[256];

    float v[8];
    float m = -3.0e38f;
    #pragma unroll
    for (int j = 0; j < 8; j++) {
        const int c = tid + j * 256;
        v[j] = (c < len) ? p[c] : -3.0e38f;
        m = fmaxf(m, v[j]);
    }
    red[tid] = m; __syncthreads();
    for (int s = 128; s > 0; s >>= 1) {
        if (tid < s) red[tid] = fmaxf(red[tid], red[tid + s]);
        __syncthreads();
    }
    m = red[0]; __syncthreads();

    float sum = 0.0f;
    #pragma unroll
    for (int j = 0; j < 8; j++) {
        const int c = tid + j * 256;
        v[j] = (c < len) ? __expf(v[j] - m) : 0.0f;
        sum += v[j];
    }
    red[tid] = sum; __syncthreads();
    for (int s = 128; s > 0; s >>= 1) {
        if (tid < s) red[tid] += red[tid + s];
        __syncthreads();
    }
    const float inv = 1.0f / red[0]; __syncthreads();

    #pragma unroll
    for (int j = 0; j < 8; j++) {
        const int c = tid + j * 256;
        p[c] = v[j] * inv;          // exact 0 above diagonal
    }
}

// ---------------- launch ----------------
extern "C" void kernel_launch(void* const* d_in, const int* in_sizes, int n_in,
                              void* d_out, int out_size)
{
    const float* hs   = (const float*)d_in[0];
    const float* cosb = (const float*)d_in[1];
    const float* sinb = (const float*)d_in[2];
    const float* Wq   = (const float*)d_in[4];
    const float* Wk   = (const float*)d_in[5];
    const float* Wv   = (const float*)d_in[6];
    const float* Wo   = (const float*)d_in[7];

    float* out_attn = (float*)d_out;                          // (B,S,H)
    float* out_w    = (float*)d_out + (long)BSZ * SEQ * HID;  // (B,NH,S,S)

    const long SS = (long)SEQ * SEQ;

    // 0) concat K/V weights
    concat_wkv<<<(HID * 512) / 256, 256>>>(Wk, Wv, g_Wkv);

    // 1) Q projection: (4096 x 2048) @ (2048 x 2048)
    sgemm2<<<dim3(16, 32, 1), 256>>>(hs, Wq, g_Qp,
        HID, HID, HID, HID, 0, 0, 0, 0, 1, 0, 0);

    // 2) KV projection: (4096 x 2048) @ (2048 x 512)
    sgemm2<<<dim3(4, 32, 1), 256>>>(hs, g_Wkv, g_KV,
        HID, HID, 512, 512, 0, 0, 0, 0, 1, 0, 0);

    // 3) RoPE Q (+transpose+scale), RoPE K (+transpose)
    rope_q <<<4096, 256>>>(g_Qp, cosb, sinb, g_Q);
    rope_kT<<<dim3(64, 8, 2), dim3(32, 32)>>>(g_KV, cosb, sinb, g_Kt);

    // 4) logits = Q K^T (scaled via Q), causal tile skip
    sgemm2<<<dim3(16, 16, 16), 256>>>(g_Q, g_Kt, out_w,
        HD, HD, SEQ, SEQ,
        (long)SEQ * HD, (long)HD * SEQ, (long)NH * SS, SS, NH, 1, 0);

    // 5) causal softmax (exact zeros above diagonal)
    softmax_causal<<<32768, 256>>>(out_w);

    // 6) attn = P @ V, K-loop truncated by causality
    sgemm2<<<dim3(2, 16, 16), 256>>>(out_w, g_KV + 256, g_AO,
        SEQ, SEQ, 512, HID,
        SS, (long)SEQ * 512, (long)SEQ * HID, (long)HD, NH, 0, 1);

    // 7) output projection: (4096 x 2048) @ (2048 x 2048)
    sgemm2<<<dim3(16, 32, 1), 256>>>(g_AO, Wo, out_attn,
        HID, HID, HID, HID, 0, 0, 0, 0, 1, 0, 0);
}